// round 2
// baseline (speedup 1.0000x reference)
#include <cuda_runtime.h>
#include <math.h>

#define S_LEN 256
#define H_DIM 768
#define D_DIM 64
#define B_SZ  64
#define NEG_N 4
#define NB    (B_SZ * NEG_N)   /* 256 */
#define EPSF  1e-15f
#define BNDF  0.9999999f       /* 1.0 - 1e-7 */

/* scratch (no allocations allowed) */
__device__ float g_U[B_SZ * D_DIM];
__device__ float g_V[B_SZ * D_DIM];
__device__ float g_N[NB * D_DIM];

/* ---------------- Stage 1: gather + expmap0 + mobius_matvec ----------------
 * One block per output vector: 64 u's, 64 v's, 256 negatives = 384 blocks.
 * The mask is one-hot over S, so masked-sum == row select; expmap0 commutes
 * with the selection.
 */
__global__ __launch_bounds__(256) void k_gather(
    const float* __restrict__ enc,   /* [B,S,H]      */
    const float* __restrict__ nenc,  /* [B*NEG,S,H]  */
    const float* __restrict__ m1,    /* [B,S]        */
    const float* __restrict__ m2,    /* [B,S]        */
    const float* __restrict__ mneg,  /* [B*NEG,S]    */
    const float* __restrict__ W)     /* [D,H]        */
{
    __shared__ __align__(16) float xs[H_DIM];
    __shared__ float red[256];
    __shared__ int   sidx;
    __shared__ float snorm2;

    const int i = blockIdx.x;
    const int t = threadIdx.x;

    const float* src; const float* mask; float* dst;
    if (i < B_SZ) {
        src = enc  + (size_t)i * S_LEN * H_DIM;  mask = m1 + i * S_LEN;  dst = g_U + i * D_DIM;
    } else if (i < 2 * B_SZ) {
        int b = i - B_SZ;
        src = enc  + (size_t)b * S_LEN * H_DIM;  mask = m2 + b * S_LEN;  dst = g_V + b * D_DIM;
    } else {
        int j = i - 2 * B_SZ;
        src = nenc + (size_t)j * S_LEN * H_DIM;  mask = mneg + j * S_LEN; dst = g_N + j * D_DIM;
    }

    /* one-hot scan: S == blockDim == 256, one compare per thread */
    if (mask[t] > 0.5f) sidx = t;
    __syncthreads();

    /* gather row into smem, accumulate ||x||^2 */
    const float* row = src + (size_t)sidx * H_DIM;
    float p = 0.f;
    #pragma unroll
    for (int h = t; h < H_DIM; h += 256) {
        float xv = row[h];
        xs[h] = xv;
        p += xv * xv;
    }
    red[t] = p;
    __syncthreads();
    for (int off = 128; off > 0; off >>= 1) {
        if (t < off) red[t] += red[t + off];
        __syncthreads();
    }
    if (t == 0) snorm2 = red[0];
    __syncthreads();

    /* matvec mx = W @ x: thread t -> output d = t&63, quarter q = t>>6 */
    const int d = t & 63;
    const int q = t >> 6;
    const float4* Wr = (const float4*)(W + (size_t)d * H_DIM + q * 192);
    const float4* xr = (const float4*)(xs + q * 192);
    float acc = 0.f;
    #pragma unroll
    for (int k = 0; k < 48; k++) {
        float4 w = Wr[k];
        float4 x = xr[k];
        acc = fmaf(w.x, x.x, fmaf(w.y, x.y, fmaf(w.z, x.z, fmaf(w.w, x.w, acc))));
    }
    red[t] = acc;
    __syncthreads();

    /* expmap0 scale: y = (tanh(n)/n) * x, n = max(||x||, eps) */
    const float xnorm = sqrtf(snorm2);
    const float n     = fmaxf(xnorm, EPSF);
    const float s1    = tanhf(n) / n;

    float mx = 0.f;
    if (t < 64) mx = (red[t] + red[t + 64] + red[t + 128] + red[t + 192]) * s1;
    __syncthreads();
    red[t] = (t < 64) ? mx * mx : 0.f;
    __syncthreads();
    for (int off = 32; off > 0; off >>= 1) {
        if (t < off) red[t] += red[t + off];
        __syncthreads();
    }

    if (t < 64) {
        const float mn2 = red[0];
        const float yn  = s1 * xnorm;              /* ||y|| */
        const float xn  = fmaxf(yn, EPSF);
        const float xc  = fminf(xn, BNDF);
        const float art = 0.5f * logf((1.f + xc) / (1.f - xc));   /* artanh */
        const float mn  = fmaxf(sqrtf(mn2), EPSF);
        const float sc  = tanhf(mn / xn * art) / mn;
        dst[t] = sc * mx;
    }
}

/* ---------------- Stage 2: loss, all from scalar reductions ---------------- */

__device__ __forceinline__ float wsum16(float x) {
    #pragma unroll
    for (int o = 8; o > 0; o >>= 1)
        x += __shfl_xor_sync(0xffffffffu, x, o, 16);
    return x;
}

/* dist(x,y) = 2*artanh(||mobius_add(-x,y)||) from scalars:
 * a = ||x||^2, b2 = ||y||^2, c = (-x).y
 * ||num||^2 = A^2 a + B^2 b2 + 2AB c,  A = 1+2c+b2, B = 1-a
 */
__device__ __forceinline__ float pdist(float a, float b2, float c) {
    const float A  = 1.f + 2.f * c + b2;
    const float Bf = 1.f - a;
    const float nn = A * A * a + Bf * Bf * b2 + 2.f * A * Bf * c;
    const float den = fmaxf(1.f + 2.f * c + a * b2, EPSF);
    float nrm = sqrtf(fmaxf(nn, 0.f)) / den;
    nrm = fminf(nrm, BNDF);
    return logf((1.f + nrm) / (1.f - nrm));   /* 2*artanh(nrm) */
}

__global__ __launch_bounds__(1024) void k_loss(float* __restrict__ out) {
    __shared__ float sl[B_SZ];
    const int t = threadIdx.x;
    const int b = t >> 4;      /* batch element: 64 groups of 16 lanes */
    const int l = t & 15;

    const float* u  = g_U + b * D_DIM;
    const float* v  = g_V + b * D_DIM;
    const float* ng = g_N + b * NEG_N * D_DIM;

    float ur[4], vr[4];
    float uu = 0.f, vv = 0.f, uv = 0.f;
    #pragma unroll
    for (int k = 0; k < 4; k++) {
        ur[k] = u[l + 16 * k];
        vr[k] = v[l + 16 * k];
        uu += ur[k] * ur[k];
        vv += vr[k] * vr[k];
        uv += ur[k] * vr[k];
    }
    uu = wsum16(uu);
    vv = wsum16(vv);
    uv = wsum16(uv);

    /* negative-sampling term */
    const float dsq    = pdist(uu, vv, -uv);
    const float expneg = expf(-dsq);
    float Z = 0.f;
    #pragma unroll
    for (int j = 0; j < NEG_N; j++) {
        float nn = 0.f, un = 0.f;
        #pragma unroll
        for (int k = 0; k < 4; k++) {
            float nv_ = ng[j * D_DIM + l + 16 * k];
            nn += nv_ * nv_;
            un += ur[k] * nv_;
        }
        nn = wsum16(nn);
        un = wsum16(un);
        Z += expf(-pdist(uu, nn, -un));
    }
    const float ns = -logf(expneg / (Z + expneg));

    /* hyperbolic angle */
    const float a0 = uu, b0 = vv, dot = uv;
    const float nv2    = sqrtf(b0);
    const float euclid = sqrtf(fmaxf(a0 + b0 - 2.f * dot, 0.f));
    const float rad    = fmaxf(1.f + a0 * b0 - 2.f * dot, EPSF);
    const float den    = fmaxf(nv2 * euclid * sqrtf(rad), EPSF);
    float ca = (dot * (1.f + b0) - b0 * (1.f + a0)) / den;
    ca = fminf(fmaxf(ca, -BNDF), BNDF);
    const float ang = acosf(ca);

    /* alpha = 0.5: loss_b = 2*(1-a)*ang + 2*a*ns = ang + ns */
    if (l == 0) sl[b] = ang + ns;
    __syncthreads();
    if (t == 0) {
        float s = 0.f;
        for (int k = 0; k < B_SZ; k++) s += sl[k];
        out[0] = s * (1.f / (float)B_SZ);
    }
}

extern "C" void kernel_launch(void* const* d_in, const int* in_sizes, int n_in,
                              void* d_out, int out_size) {
    const float *enc = nullptr, *nenc = nullptr, *m1 = nullptr,
                *m2 = nullptr, *mn = nullptr, *W = nullptr;
    /* resolve by element count (metadata order: encoded, n_encoded, mask1,
     * mask2, mask_u_neg, W). mask1/mask2 share a size -> first wins as mask1 */
    for (int i = 0; i < n_in; i++) {
        int sz = in_sizes[i];
        const float* p = (const float*)d_in[i];
        if      (sz == B_SZ * S_LEN * H_DIM) enc  = p;
        else if (sz == NB   * S_LEN * H_DIM) nenc = p;
        else if (sz == B_SZ * S_LEN)         { if (!m1) m1 = p; else m2 = p; }
        else if (sz == NB   * S_LEN)         mn = p;
        else if (sz == D_DIM * H_DIM)        W  = p;
    }

    k_gather<<<2 * B_SZ + NB, 256>>>(enc, nenc, m1, m2, mn, W);
    k_loss<<<1, 1024>>>((float*)d_out);
}

// round 3
// speedup vs baseline: 1.4699x; 1.4699x over previous
#include <cuda_runtime.h>
#include <math.h>

#define S_LEN 256
#define H_DIM 768
#define D_DIM 64
#define B_SZ  64
#define NEG_N 4
#define NB    (B_SZ * NEG_N)     /* 256 */
#define NVEC  (2 * B_SZ + NB)    /* 384 */
#define GPB   4                  /* vectors per block */
#define NBLK  (NVEC / GPB)       /* 96 */
#define EPSF  1e-15f
#define BNDF  0.9999999f         /* 1.0 - 1e-7 */

/* scratch (no allocations allowed) */
__device__ __align__(16) float g_U[B_SZ * D_DIM];
__device__ __align__(16) float g_V[B_SZ * D_DIM];
__device__ __align__(16) float g_N[NB * D_DIM];
__device__ unsigned g_cnt;       /* zero-initialized at load; last block resets */

__device__ __forceinline__ float ftanh(float x) {
    float e = __expf(2.f * x);
    return (e - 1.f) / (e + 1.f);
}
__device__ __forceinline__ float fartanh(float x) {
    return 0.5f * __logf((1.f + x) / (1.f - x));
}
/* dist(x,y) = 2*artanh(||mobius_add(-x,y)||) from scalars:
 * a = ||x||^2, b2 = ||y||^2, c = (-x).y
 * ||num||^2 = A^2 a + B^2 b2 + 2AB c,  A = 1+2c+b2, B = 1-a      */
__device__ __forceinline__ float pdist(float a, float b2, float c) {
    const float A  = 1.f + 2.f * c + b2;
    const float Bf = 1.f - a;
    const float nn = A * A * a + Bf * Bf * b2 + 2.f * A * Bf * c;
    const float den = fmaxf(1.f + 2.f * c + a * b2, EPSF);
    float nrm = fminf(sqrtf(fmaxf(nn, 0.f)) / den, BNDF);
    return __logf((1.f + nrm) / (1.f - nrm));   /* 2*artanh */
}

__global__ __launch_bounds__(256) void k_fused(
    const float* __restrict__ enc,   /* [B,S,H]     */
    const float* __restrict__ nenc,  /* [B*NEG,S,H] */
    const float* __restrict__ m1,    /* [B,S]       */
    const float* __restrict__ m2,    /* [B,S]       */
    const float* __restrict__ mneg,  /* [B*NEG,S]   */
    const float* __restrict__ W,     /* [D,H]       */
    float* __restrict__ out)
{
    __shared__ __align__(16) float xs[GPB][H_DIM];   /* 12 KB */
    __shared__ float scr[1024];                      /* 4 KB: norm partials -> gemm partials -> per-batch loss */
    __shared__ float s_norm2[GPB], s_s1[GPB];
    __shared__ int   s_idx[GPB];
    __shared__ float s_mq[2][GPB];
    __shared__ unsigned s_rank;

    const int t    = threadIdx.x;
    const int bk   = blockIdx.x;
    const int warp = t >> 5;
    const int lane = t & 31;

    /* resolve per-vector src/mask/dst */
    const float* src[GPB]; const float* msk[GPB]; float* dst[GPB];
    #pragma unroll
    for (int g = 0; g < GPB; g++) {
        int i = bk * GPB + g;
        if (i < B_SZ) {
            src[g] = enc  + (size_t)i * S_LEN * H_DIM;
            msk[g] = m1 + i * S_LEN;  dst[g] = g_U + i * D_DIM;
        } else if (i < 2 * B_SZ) {
            int b = i - B_SZ;
            src[g] = enc  + (size_t)b * S_LEN * H_DIM;
            msk[g] = m2 + b * S_LEN;  dst[g] = g_V + b * D_DIM;
        } else {
            int j = i - 2 * B_SZ;
            src[g] = nenc + (size_t)j * S_LEN * H_DIM;
            msk[g] = mneg + j * S_LEN; dst[g] = g_N + j * D_DIM;
        }
    }

    /* one-hot scan: S == blockDim == 256 */
    #pragma unroll
    for (int g = 0; g < GPB; g++)
        if (msk[g][t] > 0.5f) s_idx[g] = t;
    __syncthreads();

    /* gather rows + per-thread norm partials */
    #pragma unroll
    for (int g = 0; g < GPB; g++) {
        const float* row = src[g] + (size_t)s_idx[g] * H_DIM;
        float p = 0.f;
        #pragma unroll
        for (int h = t, k = 0; k < 3; k++, h += 256) {
            float xv = row[h];
            xs[g][h] = xv;
            p += xv * xv;
        }
        scr[g * 256 + t] = p;
    }
    __syncthreads();

    /* warp g reduces its vector's norm; computes expmap0 scale s1 = tanh(n)/n */
    if (warp < GPB) {
        float s = 0.f;
        #pragma unroll
        for (int j = 0; j < 8; j++) s += scr[warp * 256 + lane + j * 32];
        #pragma unroll
        for (int o = 16; o > 0; o >>= 1) s += __shfl_xor_sync(0xffffffffu, s, o);
        if (lane == 0) {
            s_norm2[warp] = s;
            float nx = sqrtf(s);
            float n  = fmaxf(nx, EPSF);
            s_s1[warp] = ftanh(n) / n;
        }
    }
    __syncthreads();

    /* GEMM: thread (d = t&63, q = t>>6) accumulates 4 vectors over its W chunk.
     * Within a warp all lanes share q -> smem reads broadcast. */
    const int d = t & 63;
    const int q = t >> 6;
    const float4* Wr = (const float4*)(W + (size_t)d * H_DIM + q * 192);
    float acc[GPB] = {0.f, 0.f, 0.f, 0.f};
    #pragma unroll
    for (int k = 0; k < 48; k++) {
        float4 w = Wr[k];
        #pragma unroll
        for (int g = 0; g < GPB; g++) {
            float4 x = ((const float4*)(xs[g] + q * 192))[k];
            acc[g] = fmaf(w.x, x.x, fmaf(w.y, x.y, fmaf(w.z, x.z, fmaf(w.w, x.w, acc[g]))));
        }
    }
    #pragma unroll
    for (int g = 0; g < GPB; g++)
        scr[q * 256 + g * 64 + d] = acc[g];
    __syncthreads();

    /* epilogue: combine q-partials, mobius_matvec scaling, write to scratch */
    float mx[GPB];
    if (t < 64) {
        #pragma unroll
        for (int g = 0; g < GPB; g++) {
            float s = scr[g * 64 + t] + scr[256 + g * 64 + t]
                    + scr[512 + g * 64 + t] + scr[768 + g * 64 + t];
            mx[g] = s * s_s1[g];
            float sq = mx[g] * mx[g];
            #pragma unroll
            for (int o = 16; o > 0; o >>= 1) sq += __shfl_xor_sync(0xffffffffu, sq, o);
            if (lane == 0) s_mq[warp][g] = sq;
        }
    }
    __syncthreads();
    if (t < 64) {
        #pragma unroll
        for (int g = 0; g < GPB; g++) {
            float mn2 = s_mq[0][g] + s_mq[1][g];
            float nx  = sqrtf(s_norm2[g]);
            float yn  = s_s1[g] * nx;                 /* ||expmap0(x)|| */
            float xn  = fmaxf(yn, EPSF);
            float xc  = fminf(xn, BNDF);
            float art = fartanh(xc);
            float mn  = fmaxf(sqrtf(mn2), EPSF);
            float sc  = ftanh(mn / xn * art) / mn;
            dst[g][t] = sc * mx[g];
        }
    }

    /* -------- grid-wide completion: last block computes the loss -------- */
    __threadfence();
    __syncthreads();
    if (t == 0) s_rank = atomicAdd(&g_cnt, 1u);
    __syncthreads();
    if (s_rank != NBLK - 1) return;

    /* stage 2: 64 groups of 4 lanes; lane l owns components [l*16, l*16+16) */
    {
        const int b = t >> 2;
        const int l = t & 3;
        const float* up = g_U + b * D_DIM + l * 16;
        const float* vp = g_V + b * D_DIM + l * 16;

        float ur[16], vr[16];
        float uu = 0.f, vv = 0.f, uv = 0.f;
        #pragma unroll
        for (int k4 = 0; k4 < 4; k4++) {
            float4 a = __ldcg((const float4*)(up + k4 * 4));
            float4 c = __ldcg((const float4*)(vp + k4 * 4));
            ur[k4*4+0]=a.x; ur[k4*4+1]=a.y; ur[k4*4+2]=a.z; ur[k4*4+3]=a.w;
            vr[k4*4+0]=c.x; vr[k4*4+1]=c.y; vr[k4*4+2]=c.z; vr[k4*4+3]=c.w;
            uu += a.x*a.x + a.y*a.y + a.z*a.z + a.w*a.w;
            vv += c.x*c.x + c.y*c.y + c.z*c.z + c.w*c.w;
            uv += a.x*c.x + a.y*c.y + a.z*c.z + a.w*c.w;
        }
        uu += __shfl_xor_sync(0xffffffffu, uu, 1); uu += __shfl_xor_sync(0xffffffffu, uu, 2);
        vv += __shfl_xor_sync(0xffffffffu, vv, 1); vv += __shfl_xor_sync(0xffffffffu, vv, 2);
        uv += __shfl_xor_sync(0xffffffffu, uv, 1); uv += __shfl_xor_sync(0xffffffffu, uv, 2);

        float dsq    = pdist(uu, vv, -uv);
        float expneg = __expf(-dsq);
        float Z = 0.f;
        #pragma unroll
        for (int j = 0; j < NEG_N; j++) {
            const float* ng = g_N + (size_t)(b * NEG_N + j) * D_DIM + l * 16;
            float nn = 0.f, un = 0.f;
            #pragma unroll
            for (int k4 = 0; k4 < 4; k4++) {
                float4 a = __ldcg((const float4*)(ng + k4 * 4));
                nn += a.x*a.x + a.y*a.y + a.z*a.z + a.w*a.w;
                un += ur[k4*4+0]*a.x + ur[k4*4+1]*a.y + ur[k4*4+2]*a.z + ur[k4*4+3]*a.w;
            }
            nn += __shfl_xor_sync(0xffffffffu, nn, 1); nn += __shfl_xor_sync(0xffffffffu, nn, 2);
            un += __shfl_xor_sync(0xffffffffu, un, 1); un += __shfl_xor_sync(0xffffffffu, un, 2);
            Z += __expf(-pdist(uu, nn, -un));
        }
        float ns = -__logf(expneg / (Z + expneg));

        /* hyperbolic angle */
        float nv2    = sqrtf(vv);
        float euclid = sqrtf(fmaxf(uu + vv - 2.f * uv, 0.f));
        float rad    = fmaxf(1.f + uu * vv - 2.f * uv, EPSF);
        float den    = fmaxf(nv2 * euclid * sqrtf(rad), EPSF);
        float ca = (uv * (1.f + vv) - vv * (1.f + uu)) / den;
        ca = fminf(fmaxf(ca, -BNDF), BNDF);
        float ang = acosf(ca);

        /* alpha = 0.5: loss_b = ang + ns */
        if (l == 0) scr[b] = ang + ns;
        __syncthreads();
        if (t == 0) {
            float s = 0.f;
            #pragma unroll
            for (int k = 0; k < B_SZ; k++) s += scr[k];
            out[0] = s * (1.f / (float)B_SZ);
            g_cnt  = 0;   /* reset for next (graph-replayed) launch */
        }
    }
}

extern "C" void kernel_launch(void* const* d_in, const int* in_sizes, int n_in,
                              void* d_out, int out_size) {
    const float *enc = nullptr, *nenc = nullptr, *m1 = nullptr,
                *m2 = nullptr, *mn = nullptr, *W = nullptr;
    for (int i = 0; i < n_in; i++) {
        int sz = in_sizes[i];
        const float* p = (const float*)d_in[i];
        if      (sz == B_SZ * S_LEN * H_DIM) enc  = p;
        else if (sz == NB   * S_LEN * H_DIM) nenc = p;
        else if (sz == B_SZ * S_LEN)         { if (!m1) m1 = p; else m2 = p; }
        else if (sz == NB   * S_LEN)         mn = p;
        else if (sz == D_DIM * H_DIM)        W  = p;
    }
    k_fused<<<NBLK, 256>>>(enc, nenc, m1, m2, mn, W, (float*)d_out);
}

// round 4
// speedup vs baseline: 1.6294x; 1.1085x over previous
#include <cuda_runtime.h>
#include <math.h>

#define S_LEN 256
#define H_DIM 768
#define D_DIM 64
#define B_SZ  64
#define NEG_N 4
#define NB    (B_SZ * NEG_N)     /* 256 */
#define NVEC  (2 * B_SZ + NB)    /* 384 */
#define GPB   3                  /* vectors per block */
#define NBLK  (NVEC / GPB)       /* 128 */
#define NTHR  512
#define EPSF  1e-15f
#define BNDF  0.9999999f         /* 1.0 - 1e-7 */

/* scratch (no allocations allowed) */
__device__ __align__(16) float g_U[B_SZ * D_DIM];
__device__ __align__(16) float g_V[B_SZ * D_DIM];
__device__ __align__(16) float g_N[NB * D_DIM];
__device__ unsigned g_cnt;       /* zero at load; last block resets each launch */

__device__ __forceinline__ float ftanh(float x) {
    float e = __expf(2.f * x);
    return (e - 1.f) / (e + 1.f);
}
__device__ __forceinline__ float fartanh(float x) {
    return 0.5f * __logf((1.f + x) / (1.f - x));
}
/* dist(x,y) = 2*artanh(||mobius_add(-x,y)||) from scalars:
 * a = ||x||^2, b2 = ||y||^2, c = (-x).y
 * ||num||^2 = A^2 a + B^2 b2 + 2AB c,  A = 1+2c+b2, B = 1-a      */
__device__ __forceinline__ float pdist(float a, float b2, float c) {
    const float A  = 1.f + 2.f * c + b2;
    const float Bf = 1.f - a;
    const float nn = A * A * a + Bf * Bf * b2 + 2.f * A * Bf * c;
    const float den = fmaxf(1.f + 2.f * c + a * b2, EPSF);
    float nrm = fminf(sqrtf(fmaxf(nn, 0.f)) / den, BNDF);
    return __logf((1.f + nrm) / (1.f - nrm));   /* 2*artanh */
}

__global__ __launch_bounds__(NTHR) void k_fused(
    const float* __restrict__ enc,   /* [B,S,H]     */
    const float* __restrict__ nenc,  /* [B*NEG,S,H] */
    const float* __restrict__ m1,    /* [B,S]       */
    const float* __restrict__ m2,    /* [B,S]       */
    const float* __restrict__ mneg,  /* [B*NEG,S]   */
    const float* __restrict__ W,     /* [D,H]       */
    float* __restrict__ out)
{
    __shared__ __align__(16) float xs[GPB][H_DIM];   /* 9 KB */
    __shared__ float scr[1536];                      /* 6 KB: norms -> gemm partials -> loss */
    __shared__ float s_norm2[GPB], s_s1[GPB];
    __shared__ int   s_idx[GPB];
    __shared__ float s_mq[2][GPB];
    __shared__ unsigned s_rank;

    const int t    = threadIdx.x;
    const int bk   = blockIdx.x;
    const int warp = t >> 5;
    const int lane = t & 31;

    /* resolve per-vector src/mask/dst */
    const float* src[GPB]; const float* msk[GPB]; float* dst[GPB];
    #pragma unroll
    for (int g = 0; g < GPB; g++) {
        int i = bk * GPB + g;
        if (i < B_SZ) {
            src[g] = enc  + (size_t)i * S_LEN * H_DIM;
            msk[g] = m1 + i * S_LEN;  dst[g] = g_U + i * D_DIM;
        } else if (i < 2 * B_SZ) {
            int b = i - B_SZ;
            src[g] = enc  + (size_t)b * S_LEN * H_DIM;
            msk[g] = m2 + b * S_LEN;  dst[g] = g_V + b * D_DIM;
        } else {
            int j = i - 2 * B_SZ;
            src[g] = nenc + (size_t)j * S_LEN * H_DIM;
            msk[g] = mneg + j * S_LEN; dst[g] = g_N + j * D_DIM;
        }
    }

    /* one-hot scan (S = 256, first 256 threads) */
    if (t < S_LEN) {
        #pragma unroll
        for (int g = 0; g < GPB; g++)
            if (msk[g][t] > 0.5f) s_idx[g] = t;
    }
    __syncthreads();

    /* gather rows (768 = 512 + 256 per vector) + per-g norm partials */
    #pragma unroll
    for (int g = 0; g < GPB; g++) {
        const float* row = src[g] + (size_t)s_idx[g] * H_DIM;
        float x0 = row[t];
        float x1 = (t < 256) ? row[512 + t] : 0.f;
        xs[g][t] = x0;
        if (t < 256) xs[g][512 + t] = x1;
        scr[g * 512 + t] = x0 * x0 + x1 * x1;
    }
    __syncthreads();

    /* warp g (g<3) reduces its vector's norm; s1 = tanh(n)/n */
    if (warp < GPB) {
        float s = 0.f;
        #pragma unroll
        for (int j = 0; j < 16; j++) s += scr[warp * 512 + lane + j * 32];
        #pragma unroll
        for (int o = 16; o > 0; o >>= 1) s += __shfl_xor_sync(0xffffffffu, s, o);
        if (lane == 0) {
            s_norm2[warp] = s;
            float nx = sqrtf(s);
            float n  = fmaxf(nx, EPSF);
            s_s1[warp] = ftanh(n) / n;
        }
    }
    __syncthreads();

    /* GEMM: thread (d = t&63, q = t>>6, q in 0..7) -> 24 float4 iters.
     * Within a warp all lanes share q -> smem reads broadcast. */
    const int d = t & 63;
    const int q = t >> 6;
    const float4* Wr = (const float4*)(W + (size_t)d * H_DIM + q * 96);
    float acc[GPB] = {0.f, 0.f, 0.f};
    #pragma unroll
    for (int k = 0; k < 24; k++) {
        float4 w = Wr[k];
        #pragma unroll
        for (int g = 0; g < GPB; g++) {
            float4 x = ((const float4*)(xs[g] + q * 96))[k];
            acc[g] = fmaf(w.x, x.x, fmaf(w.y, x.y, fmaf(w.z, x.z, fmaf(w.w, x.w, acc[g]))));
        }
    }
    #pragma unroll
    for (int g = 0; g < GPB; g++)
        scr[(q * GPB + g) * 64 + d] = acc[g];
    __syncthreads();

    /* epilogue: combine q-partials, mobius_matvec scaling, write scratch */
    float mx[GPB];
    if (t < 64) {
        #pragma unroll
        for (int g = 0; g < GPB; g++) {
            float s = 0.f;
            #pragma unroll
            for (int qq = 0; qq < 8; qq++) s += scr[(qq * GPB + g) * 64 + t];
            mx[g] = s * s_s1[g];
            float sq = mx[g] * mx[g];
            #pragma unroll
            for (int o = 16; o > 0; o >>= 1) sq += __shfl_xor_sync(0xffffffffu, sq, o);
            if (lane == 0) s_mq[warp][g] = sq;
        }
    }
    __syncthreads();
    if (t < 64) {
        #pragma unroll
        for (int g = 0; g < GPB; g++) {
            float mn2 = s_mq[0][g] + s_mq[1][g];
            float nx  = sqrtf(s_norm2[g]);
            float yn  = s_s1[g] * nx;                 /* ||expmap0(x)|| */
            float xn  = fmaxf(yn, EPSF);
            float xc  = fminf(xn, BNDF);
            float art = fartanh(xc);
            float mn  = fmaxf(sqrtf(mn2), EPSF);
            float sc  = ftanh(mn / xn * art) / mn;
            dst[g][t] = sc * mx[g];
        }
    }

    /* -------- grid-wide completion: last block computes the loss -------- */
    __threadfence();
    __syncthreads();
    if (t == 0) s_rank = atomicAdd(&g_cnt, 1u);
    __syncthreads();
    if (s_rank != NBLK - 1) return;

    /* stage 2: 64 groups of 8 lanes; lane l owns components [l*8, l*8+8) */
    {
        const int b = t >> 3;
        const int l = t & 7;
        const float* up = g_U + b * D_DIM + l * 8;
        const float* vp = g_V + b * D_DIM + l * 8;

        float ur[8];
        float uu = 0.f, vv = 0.f, uv = 0.f;
        #pragma unroll
        for (int k4 = 0; k4 < 2; k4++) {
            float4 a = __ldcg((const float4*)(up + k4 * 4));
            float4 c = __ldcg((const float4*)(vp + k4 * 4));
            ur[k4*4+0]=a.x; ur[k4*4+1]=a.y; ur[k4*4+2]=a.z; ur[k4*4+3]=a.w;
            uu += a.x*a.x + a.y*a.y + a.z*a.z + a.w*a.w;
            vv += c.x*c.x + c.y*c.y + c.z*c.z + c.w*c.w;
            uv += a.x*c.x + a.y*c.y + a.z*c.z + a.w*c.w;
        }
        #pragma unroll
        for (int o = 4; o > 0; o >>= 1) {
            uu += __shfl_xor_sync(0xffffffffu, uu, o, 8);
            vv += __shfl_xor_sync(0xffffffffu, vv, o, 8);
            uv += __shfl_xor_sync(0xffffffffu, uv, o, 8);
        }

        float dsq    = pdist(uu, vv, -uv);
        float expneg = __expf(-dsq);
        float Z = 0.f;
        #pragma unroll
        for (int j = 0; j < NEG_N; j++) {
            const float* ng = g_N + (size_t)(b * NEG_N + j) * D_DIM + l * 8;
            float nn = 0.f, un = 0.f;
            #pragma unroll
            for (int k4 = 0; k4 < 2; k4++) {
                float4 a = __ldcg((const float4*)(ng + k4 * 4));
                nn += a.x*a.x + a.y*a.y + a.z*a.z + a.w*a.w;
                un += ur[k4*4+0]*a.x + ur[k4*4+1]*a.y + ur[k4*4+2]*a.z + ur[k4*4+3]*a.w;
            }
            #pragma unroll
            for (int o = 4; o > 0; o >>= 1) {
                nn += __shfl_xor_sync(0xffffffffu, nn, o, 8);
                un += __shfl_xor_sync(0xffffffffu, un, o, 8);
            }
            Z += __expf(-pdist(uu, nn, -un));
        }
        float ns = -__logf(expneg / (Z + expneg));

        /* hyperbolic angle */
        float nv2    = sqrtf(vv);
        float euclid = sqrtf(fmaxf(uu + vv - 2.f * uv, 0.f));
        float rad    = fmaxf(1.f + uu * vv - 2.f * uv, EPSF);
        float den    = fmaxf(nv2 * euclid * sqrtf(rad), EPSF);
        float ca = (uv * (1.f + vv) - vv * (1.f + uu)) / den;
        ca = fminf(fmaxf(ca, -BNDF), BNDF);
        float ang = acosf(ca);

        /* alpha = 0.5: loss_b = ang + ns */
        if (l == 0) scr[b] = ang + ns;
        __syncthreads();
        if (t < 32) {
            float s = scr[t] + scr[t + 32];
            #pragma unroll
            for (int o = 16; o > 0; o >>= 1) s += __shfl_xor_sync(0xffffffffu, s, o);
            if (t == 0) {
                out[0] = s * (1.f / (float)B_SZ);
                g_cnt  = 0;   /* reset for next (graph-replayed) launch */
            }
        }
    }
}

extern "C" void kernel_launch(void* const* d_in, const int* in_sizes, int n_in,
                              void* d_out, int out_size) {
    const float *enc = nullptr, *nenc = nullptr, *m1 = nullptr,
                *m2 = nullptr, *mn = nullptr, *W = nullptr;
    for (int i = 0; i < n_in; i++) {
        int sz = in_sizes[i];
        const float* p = (const float*)d_in[i];
        if      (sz == B_SZ * S_LEN * H_DIM) enc  = p;
        else if (sz == NB   * S_LEN * H_DIM) nenc = p;
        else if (sz == B_SZ * S_LEN)         { if (!m1) m1 = p; else m2 = p; }
        else if (sz == NB   * S_LEN)         mn = p;
        else if (sz == D_DIM * H_DIM)        W  = p;
    }
    k_fused<<<NBLK, NTHR>>>(enc, nenc, m1, m2, mn, W, (float*)d_out);
}

// round 5
// speedup vs baseline: 2.0678x; 1.2691x over previous
#include <cuda_runtime.h>
#include <math.h>

#define S_LEN 256
#define H_DIM 768
#define D_DIM 64
#define B_SZ  64
#define NEG_N 4
#define NB    (B_SZ * NEG_N)     /* 256 */
#define NVEC  (2 * B_SZ + NB)    /* 384 */
#define GPB   3                  /* vectors per block */
#define NBLK  (NVEC / GPB)       /* 128 */
#define NTHR  512
#define EPSF  1e-15f
#define BNDF  0.9999999f         /* 1.0 - 1e-7 */

/* scratch (no allocations allowed) */
__device__ __align__(16) float g_U[B_SZ * D_DIM];
__device__ __align__(16) float g_V[B_SZ * D_DIM];
__device__ __align__(16) float g_N[NB * D_DIM];
__device__ unsigned g_cnt;       /* zero at load; last block resets each launch */

__device__ __forceinline__ float ftanh(float x) {
    float e = __expf(2.f * x);
    return (e - 1.f) / (e + 1.f);
}
__device__ __forceinline__ float fartanh(float x) {
    return 0.5f * __logf((1.f + x) / (1.f - x));
}
/* dist(x,y) = 2*artanh(||mobius_add(-x,y)||) from scalars:
 * a = ||x||^2, b2 = ||y||^2, c = (-x).y
 * ||num||^2 = A^2 a + B^2 b2 + 2AB c,  A = 1+2c+b2, B = 1-a      */
__device__ __forceinline__ float pdist(float a, float b2, float c) {
    const float A  = 1.f + 2.f * c + b2;
    const float Bf = 1.f - a;
    const float nn = A * A * a + Bf * Bf * b2 + 2.f * A * Bf * c;
    const float den = fmaxf(1.f + 2.f * c + a * b2, EPSF);
    float nrm = fminf(sqrtf(fmaxf(nn, 0.f)) / den, BNDF);
    return __logf((1.f + nrm) / (1.f - nrm));   /* 2*artanh */
}

__global__ __launch_bounds__(NTHR) void k_fused(
    const float* __restrict__ enc,   /* [B,S,H]     */
    const float* __restrict__ nenc,  /* [B*NEG,S,H] */
    const float* __restrict__ m1,    /* [B,S]       */
    const float* __restrict__ m2,    /* [B,S]       */
    const float* __restrict__ mneg,  /* [B*NEG,S]   */
    const float* __restrict__ W,     /* [D,H]       */
    float* __restrict__ out)
{
    __shared__ __align__(16) float xs[GPB][H_DIM];   /* 9 KB */
    __shared__ float scr[1536];                      /* norms -> gemm results -> loss */
    __shared__ float s_norm2[GPB], s_s1[GPB];
    __shared__ int   s_idx[GPB];
    __shared__ float s_mq[2][GPB];
    __shared__ unsigned s_rank;

    const int t    = threadIdx.x;
    const int bk   = blockIdx.x;
    const int warp = t >> 5;
    const int lane = t & 31;

    /* resolve per-vector src/mask/dst */
    const float* src[GPB]; const float* msk[GPB]; float* dst[GPB];
    #pragma unroll
    for (int g = 0; g < GPB; g++) {
        int i = bk * GPB + g;
        if (i < B_SZ) {
            src[g] = enc  + (size_t)i * S_LEN * H_DIM;
            msk[g] = m1 + i * S_LEN;  dst[g] = g_U + i * D_DIM;
        } else if (i < 2 * B_SZ) {
            int b = i - B_SZ;
            src[g] = enc  + (size_t)b * S_LEN * H_DIM;
            msk[g] = m2 + b * S_LEN;  dst[g] = g_V + b * D_DIM;
        } else {
            int j = i - 2 * B_SZ;
            src[g] = nenc + (size_t)j * S_LEN * H_DIM;
            msk[g] = mneg + j * S_LEN; dst[g] = g_N + j * D_DIM;
        }
    }

    /* one-hot scan (S = 256, first 256 threads) */
    if (t < S_LEN) {
        #pragma unroll
        for (int g = 0; g < GPB; g++)
            if (msk[g][t] > 0.5f) s_idx[g] = t;
    }
    __syncthreads();

    /* gather rows (768 = 512 + 256 per vector) + per-g norm partials */
    #pragma unroll
    for (int g = 0; g < GPB; g++) {
        const float* row = src[g] + (size_t)s_idx[g] * H_DIM;
        float x0 = row[t];
        float x1 = (t < 256) ? row[512 + t] : 0.f;
        xs[g][t] = x0;
        if (t < 256) xs[g][512 + t] = x1;
        scr[g * 512 + t] = x0 * x0 + x1 * x1;
    }
    __syncthreads();

    /* warp g (g<3) reduces its vector's norm -> s1 = tanh(n)/n.
     * All warps concurrently run the GEMM; s1 is consumed only after the
     * next __syncthreads(). */
    if (warp < GPB) {
        float s = 0.f;
        #pragma unroll
        for (int j = 0; j < 16; j++) s += scr[warp * 512 + lane + j * 32];
        #pragma unroll
        for (int o = 16; o > 0; o >>= 1) s += __shfl_xor_sync(0xffffffffu, s, o);
        if (lane == 0) {
            s_norm2[warp] = s;
            float nx = sqrtf(s);
            float n  = fmaxf(nx, EPSF);
            s_s1[warp] = ftanh(n) / n;
        }
    }

    /* GEMM, coalesced: warp owns 4 output rows (d = warp*4 + lane>>3),
     * 8 lanes sweep H contiguously -> each warp LDG touches 4 x 128B lines. */
    {
        const int sub = lane >> 3;          /* 0..3  */
        const int l8  = lane & 7;           /* 0..7  */
        const int d   = warp * 4 + sub;     /* 0..63 */
        const float4* Wr = (const float4*)(W + (size_t)d * H_DIM) + l8;
        float acc[GPB] = {0.f, 0.f, 0.f};
        #pragma unroll
        for (int k = 0; k < 24; k++) {
            float4 w = Wr[k * 8];
            #pragma unroll
            for (int g = 0; g < GPB; g++) {
                float4 x = ((const float4*)xs[g])[k * 8 + l8];
                acc[g] = fmaf(w.x, x.x, fmaf(w.y, x.y, fmaf(w.z, x.z, fmaf(w.w, x.w, acc[g]))));
            }
        }
        #pragma unroll
        for (int g = 0; g < GPB; g++) {
            #pragma unroll
            for (int o = 4; o > 0; o >>= 1)
                acc[g] += __shfl_xor_sync(0xffffffffu, acc[g], o, 8);
            if (l8 == 0) scr[g * 64 + d] = acc[g];
        }
    }
    __syncthreads();

    /* epilogue: mobius_matvec scaling, write scratch */
    float mx[GPB];
    if (t < 64) {
        #pragma unroll
        for (int g = 0; g < GPB; g++) {
            mx[g] = scr[g * 64 + t] * s_s1[g];
            float sq = mx[g] * mx[g];
            #pragma unroll
            for (int o = 16; o > 0; o >>= 1) sq += __shfl_xor_sync(0xffffffffu, sq, o);
            if (lane == 0) s_mq[warp][g] = sq;
        }
    }
    __syncthreads();
    if (t < 64) {
        #pragma unroll
        for (int g = 0; g < GPB; g++) {
            float mn2 = s_mq[0][g] + s_mq[1][g];
            float nx  = sqrtf(s_norm2[g]);
            float yn  = s_s1[g] * nx;                 /* ||expmap0(x)|| */
            float xn  = fmaxf(yn, EPSF);
            float xc  = fminf(xn, BNDF);
            float art = fartanh(xc);
            float mn  = fmaxf(sqrtf(mn2), EPSF);
            float sc  = ftanh(mn / xn * art) / mn;
            dst[g][t] = sc * mx[g];
        }
    }

    /* -------- grid-wide completion: last block computes the loss -------- */
    __threadfence();
    __syncthreads();
    if (t == 0) s_rank = atomicAdd(&g_cnt, 1u);
    __syncthreads();
    if (s_rank != NBLK - 1) return;

    /* stage 2: 64 groups of 8 lanes; lane l owns components [l*8, l*8+8) */
    {
        const int b = t >> 3;
        const int l = t & 7;
        const float* up = g_U + b * D_DIM + l * 8;
        const float* vp = g_V + b * D_DIM + l * 8;

        float ur[8];
        float uu = 0.f, vv = 0.f, uv = 0.f;
        #pragma unroll
        for (int k4 = 0; k4 < 2; k4++) {
            float4 a = __ldcg((const float4*)(up + k4 * 4));
            float4 c = __ldcg((const float4*)(vp + k4 * 4));
            ur[k4*4+0]=a.x; ur[k4*4+1]=a.y; ur[k4*4+2]=a.z; ur[k4*4+3]=a.w;
            uu += a.x*a.x + a.y*a.y + a.z*a.z + a.w*a.w;
            vv += c.x*c.x + c.y*c.y + c.z*c.z + c.w*c.w;
            uv += a.x*c.x + a.y*c.y + a.z*c.z + a.w*c.w;
        }
        #pragma unroll
        for (int o = 4; o > 0; o >>= 1) {
            uu += __shfl_xor_sync(0xffffffffu, uu, o, 8);
            vv += __shfl_xor_sync(0xffffffffu, vv, o, 8);
            uv += __shfl_xor_sync(0xffffffffu, uv, o, 8);
        }

        float dsq    = pdist(uu, vv, -uv);
        float expneg = __expf(-dsq);
        float Z = 0.f;
        #pragma unroll
        for (int j = 0; j < NEG_N; j++) {
            const float* ng = g_N + (size_t)(b * NEG_N + j) * D_DIM + l * 8;
            float nn = 0.f, un = 0.f;
            #pragma unroll
            for (int k4 = 0; k4 < 2; k4++) {
                float4 a = __ldcg((const float4*)(ng + k4 * 4));
                nn += a.x*a.x + a.y*a.y + a.z*a.z + a.w*a.w;
                un += ur[k4*4+0]*a.x + ur[k4*4+1]*a.y + ur[k4*4+2]*a.z + ur[k4*4+3]*a.w;
            }
            #pragma unroll
            for (int o = 4; o > 0; o >>= 1) {
                nn += __shfl_xor_sync(0xffffffffu, nn, o, 8);
                un += __shfl_xor_sync(0xffffffffu, un, o, 8);
            }
            Z += __expf(-pdist(uu, nn, -un));
        }
        float ns = -__logf(expneg / (Z + expneg));

        /* hyperbolic angle */
        float nv2    = sqrtf(vv);
        float euclid = sqrtf(fmaxf(uu + vv - 2.f * uv, 0.f));
        float rad    = fmaxf(1.f + uu * vv - 2.f * uv, EPSF);
        float den    = fmaxf(nv2 * euclid * sqrtf(rad), EPSF);
        float ca = (uv * (1.f + vv) - vv * (1.f + uu)) / den;
        ca = fminf(fmaxf(ca, -BNDF), BNDF);
        float ang = acosf(ca);

        /* alpha = 0.5: loss_b = ang + ns */
        if (l == 0) scr[b] = ang + ns;
        __syncthreads();
        if (t < 32) {
            float s = scr[t] + scr[t + 32];
            #pragma unroll
            for (int o = 16; o > 0; o >>= 1) s += __shfl_xor_sync(0xffffffffu, s, o);
            if (t == 0) {
                out[0] = s * (1.f / (float)B_SZ);
                g_cnt  = 0;   /* reset for next (graph-replayed) launch */
            }
        }
    }
}

extern "C" void kernel_launch(void* const* d_in, const int* in_sizes, int n_in,
                              void* d_out, int out_size) {
    const float *enc = nullptr, *nenc = nullptr, *m1 = nullptr,
                *m2 = nullptr, *mn = nullptr, *W = nullptr;
    for (int i = 0; i < n_in; i++) {
        int sz = in_sizes[i];
        const float* p = (const float*)d_in[i];
        if      (sz == B_SZ * S_LEN * H_DIM) enc  = p;
        else if (sz == NB   * S_LEN * H_DIM) nenc = p;
        else if (sz == B_SZ * S_LEN)         { if (!m1) m1 = p; else m2 = p; }
        else if (sz == NB   * S_LEN)         mn = p;
        else if (sz == D_DIM * H_DIM)        W  = p;
    }
    k_fused<<<NBLK, NTHR>>>(enc, nenc, m1, m2, mn, W, (float*)d_out);
}